// round 14
// baseline (speedup 1.0000x reference)
#include <cuda_runtime.h>
#include <cuda_bf16.h>
#include <cstdint>

// ---------------------------------------------------------------------------
// Batch-1 GRU (only batch element 1023 feeds the head), T=512, H=128, 4 layers.
// Wavefront pipeline, one persistent kernel, 20 CTAs:
//   role 0..3   : rec CTA for layer l=role (W_hh rows in registers)
//   role 4..15  : gi CTAs, layer l=1..3 x 4 t-phases (W_ih rows in registers)
//   role 16..19 : FC head CTAs, 4 t-phases
// R14 = R9 base (DHOR=6 ring, deferred-STS, smem-staged gi CTAs) with the
// rec-loop flag mechanism replaced:
//   * NO ld.acquire in the rec loop (acquire ordering was stalling the dot's
//     LDS reads behind a full L2 round trip every step -> late to BAR1).
//   * Every thread polls f_gi(t+DHOR) with ld.relaxed.gpu in the gate phase
//     and orders the gi data load via an asm-laundered ADDRESS DEPENDENCY on
//     the flag value. Both L2 round trips live in the one-step slack.
// ---------------------------------------------------------------------------

#define T_STEPS 512
#define HID 128
#define G3   384
#define FPAD 32     // ints per flag -> one 128B line per flag
#define DEPTH 8     // gi ring slots (power of 2)
#define DHOR  6     // flag horizon: step t readies flag(t+DHOR)

__device__ float g_H[4 * T_STEPS * HID];
__device__ float g_GI[3 * T_STEPS * G3];
__device__ int   f_h[4 * T_STEPS * FPAD];
__device__ int   f_gi[4 * T_STEPS * FPAD];

static __device__ __forceinline__ int fh_idx(int l, int t) { return (l * T_STEPS + t) * FPAD; }
static __device__ __forceinline__ int fg_idx(int l, int t) { return (l * T_STEPS + t) * FPAD; }

static __device__ __forceinline__ float fast_sigmoid(float x) {
    return __fdividef(1.0f, 1.0f + __expf(-x));
}
static __device__ __forceinline__ float fast_tanh(float x) {
    float e = __expf(2.0f * x);
    return 1.0f - __fdividef(2.0f, e + 1.0f);
}
static __device__ __forceinline__ float f32x2_lo(unsigned long long v) {
    return __uint_as_float((unsigned int)(v & 0xffffffffu));
}
static __device__ __forceinline__ float f32x2_hi(unsigned long long v) {
    return __uint_as_float((unsigned int)(v >> 32));
}
static __device__ __forceinline__ void st_release(int* p, int v) {
    asm volatile("st.release.gpu.global.s32 [%0], %1;" :: "l"(p), "r"(v) : "memory");
}
static __device__ __forceinline__ int ld_acquire(const int* p) {
    int v;
    asm volatile("ld.acquire.gpu.global.s32 %0, [%1];" : "=r"(v) : "l"(p) : "memory");
    return v;
}
static __device__ __forceinline__ int ld_relaxed(const int* p) {
    int v;
    asm volatile("ld.relaxed.gpu.global.s32 %0, [%1];" : "=r"(v) : "l"(p) : "memory");
    return v;
}
// opaque zero derived from f: forces the consumer load's address to depend on
// the flag load's RESULT (load-after-load via register dependency, no fence)
static __device__ __forceinline__ uint32_t dep_zero(int f) {
    uint32_t z;
    asm("and.b32 %0, %1, 0;" : "=r"(z) : "r"(f));
    return z;
}
static __device__ __forceinline__ void spin_until(const int* p) {
    while (ld_acquire(p) == 0) { }
}

static __device__ __forceinline__ float dot128(const unsigned long long* w,
                                               const float* sh_vec) {
    unsigned long long a0 = 0ull, a1 = 0ull, a2 = 0ull, a3 = 0ull;
    const ulonglong2* h2 = reinterpret_cast<const ulonglong2*>(sh_vec);
#pragma unroll
    for (int kk = 0; kk < 16; kk++) {
        ulonglong2 hv0 = h2[2 * kk];
        ulonglong2 hv1 = h2[2 * kk + 1];
        asm("fma.rn.f32x2 %0, %1, %2, %0;" : "+l"(a0) : "l"(w[4 * kk + 0]), "l"(hv0.x));
        asm("fma.rn.f32x2 %0, %1, %2, %0;" : "+l"(a1) : "l"(w[4 * kk + 1]), "l"(hv0.y));
        asm("fma.rn.f32x2 %0, %1, %2, %0;" : "+l"(a2) : "l"(w[4 * kk + 2]), "l"(hv1.x));
        asm("fma.rn.f32x2 %0, %1, %2, %0;" : "+l"(a3) : "l"(w[4 * kk + 3]), "l"(hv1.y));
    }
    unsigned long long s01, s23, s;
    asm("add.rn.f32x2 %0, %1, %2;" : "=l"(s01) : "l"(a0), "l"(a1));
    asm("add.rn.f32x2 %0, %1, %2;" : "=l"(s23) : "l"(a2), "l"(a3));
    asm("add.rn.f32x2 %0, %1, %2;" : "=l"(s)   : "l"(s01), "l"(s23));
    return f32x2_lo(s) + f32x2_hi(s);
}

static __device__ __forceinline__ void load_row128(unsigned long long* w,
                                                   const float* row) {
    const ulonglong2* wr = reinterpret_cast<const ulonglong2*>(row);
#pragma unroll
    for (int kk = 0; kk < 32; kk++) {
        ulonglong2 v = wr[kk];
        w[2 * kk]     = v.x;
        w[2 * kk + 1] = v.y;
    }
}

__global__ void reset_flags_kernel() {
    int i = blockIdx.x * blockDim.x + threadIdx.x;
    if (i < 4 * T_STEPS) { f_h[i * FPAD] = 0; f_gi[i * FPAD] = 0; }
}

// ---------------------------------------------------------------------------
__global__ void __launch_bounds__(G3, 1)
pipeline_kernel(const float* __restrict__ x,         // (512,2,1024)
                const float* __restrict__ W_ih0,     // (384,2)
                const float* __restrict__ W_ih_rest, // (3,384,128)
                const float* __restrict__ W_hh,      // (4,384,128)
                const float* __restrict__ b_ih,      // (4,384)
                const float* __restrict__ b_hh,      // (4,384)
                const float* __restrict__ fc1_w,     // (128,128)
                const float* __restrict__ fc1_b,     // (128)
                const float* __restrict__ fc2_w,     // (3,128)
                const float* __restrict__ fc2_b,     // (3)
                float* __restrict__ out)             // (512,3)
{
    const int role = blockIdx.x;
    const int j = threadIdx.x;

    if (role < 4) {
        // ================= rec CTA, layer l = role =========================
        const int l = role;
        __shared__ __align__(16) float sh_h[HID];
        __shared__ float sh_gh[G3];
        __shared__ float sh_gi[DEPTH][G3];    // gi ring
        __shared__ float sh_x[2 * T_STEPS];   // layer 0 only

        unsigned long long w[64];
        load_row128(w, W_hh + ((size_t)l * G3 + j) * HID);
        const float bh = b_hh[l * G3 + j];

        float w0 = 0.f, w1 = 0.f, bi0 = 0.f;
        if (l == 0) {
            w0 = W_ih0[j * 2];
            w1 = W_ih0[j * 2 + 1];
            bi0 = b_ih[j];
            for (int i = j; i < 2 * T_STEPS; i += G3) {
                int t = i >> 1, c = i & 1;
                sh_x[i] = __ldg(x + (size_t)t * 2048 + c * 1024 + 1023);
            }
        }
        const float* gi_in = (l > 0) ? (g_GI + (size_t)(l - 1) * T_STEPS * G3) : nullptr;
        float* h_out = g_H + (size_t)l * T_STEPS * HID;

        // ---- prologue: zero h; acquire flags 0..DHOR-1 (one-time); stage
        //      ring slots 0..DHOR-2; reg_g = gi(DHOR-1)
        if (j < HID) sh_h[j] = 0.0f;
        if (l > 0 && j == 383) {
#pragma unroll 1
            for (int tt = 0; tt < DHOR; tt++) spin_until(&f_gi[fg_idx(l, tt)]);
        }
        __syncthreads();
#pragma unroll
        for (int tt = 0; tt < DHOR - 1; tt++) {
            float g;
            if (l == 0) {
                g = fmaf(w0, sh_x[2 * tt], fmaf(w1, sh_x[2 * tt + 1], bi0));
            } else {
                g = gi_in[(size_t)tt * G3 + j];
            }
            sh_gi[tt][j] = g;
        }
        float reg_g;   // holds gi(t + DHOR - 1) during step t
        if (l == 0) {
            reg_g = fmaf(w0, sh_x[2 * (DHOR - 1)],
                         fmaf(w1, sh_x[2 * (DHOR - 1) + 1], bi0));
        } else {
            reg_g = gi_in[(size_t)(DHOR - 1) * G3 + j];
        }
        __syncthreads();

        for (int t = 0; t < T_STEPS; t++) {
            // -------- phase A: the matvec burst (no flag ops, no acquires)
            float s = dot128(w, sh_h);
            sh_gh[j] = s + bh;
            __syncthreads();   // BAR1: gh ready

            // -------- phase B (slack zone): ring STS, relaxed poll + dep load
            if (t + DHOR - 1 < T_STEPS)
                sh_gi[(t + DHOR - 1) & (DEPTH - 1)][j] = reg_g;
            if (t + DHOR < T_STEPS) {
                if (l == 0) {
                    reg_g = fmaf(w0, sh_x[2 * (t + DHOR)],
                                 fmaf(w1, sh_x[2 * (t + DHOR) + 1], bi0));
                } else {
                    // relaxed poll: no HW ordering => no pipeline stall
                    const int* fp = &f_gi[fg_idx(l, t + DHOR)];
                    int f = ld_relaxed(fp);
                    while (f == 0) f = ld_relaxed(fp);      // rare in steady state
                    // address depends on flag value -> load-after-load ordering
                    reg_g = __ldg(gi_in + (size_t)(t + DHOR) * G3 + j + dep_zero(f));
                }
            }

            if (j < HID) {
                const float* gi_t = sh_gi[t & (DEPTH - 1)];
                float ghr = sh_gh[j];
                float ghz = sh_gh[j + HID];
                float ghn = sh_gh[j + 2 * HID];
                float r = fast_sigmoid(gi_t[j] + ghr);
                float z = fast_sigmoid(gi_t[j + HID] + ghz);
                float n = fast_tanh(fmaf(r, ghn, gi_t[j + 2 * HID]));
                float hnew = fmaf(z, sh_h[j] - n, n);
                sh_h[j] = hnew;
                h_out[t * HID + j] = hnew;
            }
            __syncthreads();   // BAR2: new h + ring slot staged
            if (j == 0) st_release(&f_h[fh_idx(l, t)], 1);
        }
    } else if (role < 16) {
        // ================= gi CTA: layer l, 4 t-phases =====================
        const int idx = role - 4;
        const int l = idx / 4 + 1;          // 1..3
        const int phase = idx % 4;
        __shared__ __align__(16) float sh_h[HID];

        unsigned long long w[64];
        load_row128(w, W_ih_rest + ((size_t)(l - 1) * G3 + j) * HID);
        const float bi = b_ih[l * G3 + j];
        float* gi_out = g_GI + (size_t)(l - 1) * T_STEPS * G3;
        const float* h_in = g_H + (size_t)(l - 1) * T_STEPS * HID;

        for (int t = phase; t < T_STEPS; t += 4) {
            spin_until(&f_h[fh_idx(l - 1, t)]);   // all threads spin (broadcast)
            if (j < 32) {
                reinterpret_cast<float4*>(sh_h)[j] =
                    reinterpret_cast<const float4*>(h_in + t * HID)[j];
            }
            __syncthreads();
            gi_out[(size_t)t * G3 + j] = dot128(w, sh_h) + bi;
            __syncthreads();
            if (j == 0) st_release(&f_gi[fg_idx(l, t)], 1);
        }
    } else {
        // ================= FC head CTA: 4 t-phases =========================
        const int phase = role - 16;
        __shared__ __align__(16) float sh_h[HID];
        __shared__ float sh_hid[HID];

        unsigned long long w[64];
        float b1 = 0.f;
        if (j < HID) {
            load_row128(w, fc1_w + (size_t)j * HID);
            b1 = fc1_b[j];
        }
        const float* h_in = g_H + (size_t)3 * T_STEPS * HID;

        for (int t = phase; t < T_STEPS; t += 4) {
            spin_until(&f_h[fh_idx(3, t)]);       // all threads spin
            if (j < 32) {
                reinterpret_cast<float4*>(sh_h)[j] =
                    reinterpret_cast<const float4*>(h_in + t * HID)[j];
            }
            __syncthreads();
            if (j < HID) {
                sh_hid[j] = fmaxf(dot128(w, sh_h) + b1, 0.0f);
            }
            __syncthreads();
            if (j < 96) {
                int i = j >> 5;          // output row 0..2
                int lane = j & 31;
                float p = 0.f;
#pragma unroll
                for (int k = 0; k < 4; k++) {
                    int c = lane + 32 * k;
                    p = fmaf(__ldg(fc2_w + i * HID + c), sh_hid[c], p);
                }
#pragma unroll
                for (int off = 16; off > 0; off >>= 1)
                    p += __shfl_down_sync(0xffffffffu, p, off);
                if (lane == 0) out[t * 3 + i] = p + __ldg(fc2_b + i);
            }
            __syncthreads();
        }
    }
}

// ---------------------------------------------------------------------------
extern "C" void kernel_launch(void* const* d_in, const int* in_sizes, int n_in,
                              void* d_out, int out_size) {
    const float* x         = (const float*)d_in[0];
    const float* W_ih0     = (const float*)d_in[1];
    const float* W_ih_rest = (const float*)d_in[2];
    const float* W_hh      = (const float*)d_in[3];
    const float* b_ih      = (const float*)d_in[4];
    const float* b_hh      = (const float*)d_in[5];
    const float* fc1_w     = (const float*)d_in[6];
    const float* fc1_b     = (const float*)d_in[7];
    const float* fc2_w     = (const float*)d_in[8];
    const float* fc2_b     = (const float*)d_in[9];
    float* out = (float*)d_out;
    (void)in_sizes; (void)n_in; (void)out_size;

    reset_flags_kernel<<<8, 512>>>();
    pipeline_kernel<<<20, G3>>>(x, W_ih0, W_ih_rest, W_hh, b_ih, b_hh,
                                fc1_w, fc1_b, fc2_w, fc2_b, out);
}

// round 15
// speedup vs baseline: 1.2153x; 1.2153x over previous
#include <cuda_runtime.h>
#include <cuda_bf16.h>
#include <cstdint>

// ---------------------------------------------------------------------------
// Batch-1 GRU (only batch element 1023 feeds the head), T=512, H=128, 4 layers.
// Wavefront pipeline, one persistent kernel, 20 CTAs:
//   role 0..3   : rec CTA for layer l=role (W_hh rows in registers)
//   role 4..15  : gi CTAs, layer l=1..3 x 4 t-phases (W_ih rows in registers)
//   role 16..19 : FC head CTAs, 4 t-phases
// R15 = R9 verbatim EXCEPT all in-loop flag polls are ld.relaxed.gpu:
//   * rec warp-11 pre-check: relaxed (acquire was blocking its dot LDS behind
//     a ~300cyc L2 round trip every step -> late to BAR1 -> +300 cyc/step).
//   * gi/FC spins: relaxed (same ordering stall on the h staging loads).
// Safety: all consumed data addresses are first-touch on the consumer SM;
// producer st.release orders data<flag in L2; flag observation precedes the
// data loads via __syncthreads (CTA fence) or same-thread branch dependency.
// ---------------------------------------------------------------------------

#define T_STEPS 512
#define HID 128
#define G3   384
#define FPAD 32     // ints per flag -> one 128B line per flag
#define DEPTH 8     // gi ring slots (power of 2)
#define DHOR  6     // flag horizon: step t readies flag(t+DHOR)

__device__ float g_H[4 * T_STEPS * HID];
__device__ float g_GI[3 * T_STEPS * G3];
__device__ int   f_h[4 * T_STEPS * FPAD];
__device__ int   f_gi[4 * T_STEPS * FPAD];

static __device__ __forceinline__ int fh_idx(int l, int t) { return (l * T_STEPS + t) * FPAD; }
static __device__ __forceinline__ int fg_idx(int l, int t) { return (l * T_STEPS + t) * FPAD; }

static __device__ __forceinline__ float fast_sigmoid(float x) {
    return __fdividef(1.0f, 1.0f + __expf(-x));
}
static __device__ __forceinline__ float fast_tanh(float x) {
    float e = __expf(2.0f * x);
    return 1.0f - __fdividef(2.0f, e + 1.0f);
}
static __device__ __forceinline__ float f32x2_lo(unsigned long long v) {
    return __uint_as_float((unsigned int)(v & 0xffffffffu));
}
static __device__ __forceinline__ float f32x2_hi(unsigned long long v) {
    return __uint_as_float((unsigned int)(v >> 32));
}
static __device__ __forceinline__ void st_release(int* p, int v) {
    asm volatile("st.release.gpu.global.s32 [%0], %1;" :: "l"(p), "r"(v) : "memory");
}
static __device__ __forceinline__ int ld_acquire(const int* p) {
    int v;
    asm volatile("ld.acquire.gpu.global.s32 %0, [%1];" : "=r"(v) : "l"(p) : "memory");
    return v;
}
static __device__ __forceinline__ int ld_relaxed(const int* p) {
    int v;
    asm volatile("ld.relaxed.gpu.global.s32 %0, [%1];" : "=r"(v) : "l"(p) : "memory");
    return v;
}
static __device__ __forceinline__ void spin_until_acq(const int* p) {
    while (ld_acquire(p) == 0) { }
}
static __device__ __forceinline__ void spin_until_rlx(const int* p) {
    while (ld_relaxed(p) == 0) { }
}

static __device__ __forceinline__ float dot128(const unsigned long long* w,
                                               const float* sh_vec) {
    unsigned long long a0 = 0ull, a1 = 0ull, a2 = 0ull, a3 = 0ull;
    const ulonglong2* h2 = reinterpret_cast<const ulonglong2*>(sh_vec);
#pragma unroll
    for (int kk = 0; kk < 16; kk++) {
        ulonglong2 hv0 = h2[2 * kk];
        ulonglong2 hv1 = h2[2 * kk + 1];
        asm("fma.rn.f32x2 %0, %1, %2, %0;" : "+l"(a0) : "l"(w[4 * kk + 0]), "l"(hv0.x));
        asm("fma.rn.f32x2 %0, %1, %2, %0;" : "+l"(a1) : "l"(w[4 * kk + 1]), "l"(hv0.y));
        asm("fma.rn.f32x2 %0, %1, %2, %0;" : "+l"(a2) : "l"(w[4 * kk + 2]), "l"(hv1.x));
        asm("fma.rn.f32x2 %0, %1, %2, %0;" : "+l"(a3) : "l"(w[4 * kk + 3]), "l"(hv1.y));
    }
    unsigned long long s01, s23, s;
    asm("add.rn.f32x2 %0, %1, %2;" : "=l"(s01) : "l"(a0), "l"(a1));
    asm("add.rn.f32x2 %0, %1, %2;" : "=l"(s23) : "l"(a2), "l"(a3));
    asm("add.rn.f32x2 %0, %1, %2;" : "=l"(s)   : "l"(s01), "l"(s23));
    return f32x2_lo(s) + f32x2_hi(s);
}

static __device__ __forceinline__ void load_row128(unsigned long long* w,
                                                   const float* row) {
    const ulonglong2* wr = reinterpret_cast<const ulonglong2*>(row);
#pragma unroll
    for (int kk = 0; kk < 32; kk++) {
        ulonglong2 v = wr[kk];
        w[2 * kk]     = v.x;
        w[2 * kk + 1] = v.y;
    }
}

__global__ void reset_flags_kernel() {
    int i = blockIdx.x * blockDim.x + threadIdx.x;
    if (i < 4 * T_STEPS) { f_h[i * FPAD] = 0; f_gi[i * FPAD] = 0; }
}

// ---------------------------------------------------------------------------
__global__ void __launch_bounds__(G3, 1)
pipeline_kernel(const float* __restrict__ x,         // (512,2,1024)
                const float* __restrict__ W_ih0,     // (384,2)
                const float* __restrict__ W_ih_rest, // (3,384,128)
                const float* __restrict__ W_hh,      // (4,384,128)
                const float* __restrict__ b_ih,      // (4,384)
                const float* __restrict__ b_hh,      // (4,384)
                const float* __restrict__ fc1_w,     // (128,128)
                const float* __restrict__ fc1_b,     // (128)
                const float* __restrict__ fc2_w,     // (3,128)
                const float* __restrict__ fc2_b,     // (3)
                float* __restrict__ out)             // (512,3)
{
    const int role = blockIdx.x;
    const int j = threadIdx.x;

    if (role < 4) {
        // ================= rec CTA, layer l = role =========================
        const int l = role;
        __shared__ __align__(16) float sh_h[HID];
        __shared__ float sh_gh[G3];
        __shared__ float sh_gi[DEPTH][G3];    // gi ring
        __shared__ float sh_x[2 * T_STEPS];   // layer 0 only

        unsigned long long w[64];
        load_row128(w, W_hh + ((size_t)l * G3 + j) * HID);
        const float bh = b_hh[l * G3 + j];

        float w0 = 0.f, w1 = 0.f, bi0 = 0.f;
        if (l == 0) {
            w0 = W_ih0[j * 2];
            w1 = W_ih0[j * 2 + 1];
            bi0 = b_ih[j];
            for (int i = j; i < 2 * T_STEPS; i += G3) {
                int t = i >> 1, c = i & 1;
                sh_x[i] = __ldg(x + (size_t)t * 2048 + c * 1024 + 1023);
            }
        }
        const float* gi_in = (l > 0) ? (g_GI + (size_t)(l - 1) * T_STEPS * G3) : nullptr;
        float* h_out = g_H + (size_t)l * T_STEPS * HID;

        // ---- prologue: zero h; acquire flags 0..DHOR-1 (one-time); stage
        //      ring slots 0..DHOR-2; reg_g = gi(DHOR-1)
        if (j < HID) sh_h[j] = 0.0f;
        if (l > 0 && j == 383) {
#pragma unroll 1
            for (int tt = 0; tt < DHOR; tt++) spin_until_acq(&f_gi[fg_idx(l, tt)]);
        }
        __syncthreads();
#pragma unroll
        for (int tt = 0; tt < DHOR - 1; tt++) {
            float g;
            if (l == 0) {
                g = fmaf(w0, sh_x[2 * tt], fmaf(w1, sh_x[2 * tt + 1], bi0));
            } else {
                g = gi_in[(size_t)tt * G3 + j];
            }
            sh_gi[tt][j] = g;
        }
        float reg_g;   // holds gi(t + DHOR - 1) during step t
        if (l == 0) {
            reg_g = fmaf(w0, sh_x[2 * (DHOR - 1)],
                         fmaf(w1, sh_x[2 * (DHOR - 1) + 1], bi0));
        } else {
            reg_g = gi_in[(size_t)(DHOR - 1) * G3 + j];
        }
        __syncthreads();

        for (int t = 0; t < T_STEPS; t++) {
            // RELAXED pre-check: no ordering -> does NOT block the dot's LDS.
            // Value consumed only in the branch after the dot (latency hidden).
            int ready = 1;
            if (l > 0 && j == 383 && t + DHOR < T_STEPS)
                ready = ld_relaxed(&f_gi[fg_idx(l, t + DHOR)]);

            float s = dot128(w, sh_h);
            sh_gh[j] = s + bh;

            if (l > 0 && j == 383 && t + DHOR < T_STEPS && !ready)
                spin_until_rlx(&f_gi[fg_idx(l, t + DHOR)]);
            __syncthreads();   // BAR1: gh ready; flag(t+DHOR) observed CTA-wide

            // deferred STS: reg_g = gi(t+DHOR-1) -> ring; then LDG gi(t+DHOR)
            if (t + DHOR - 1 < T_STEPS)
                sh_gi[(t + DHOR - 1) & (DEPTH - 1)][j] = reg_g;
            if (t + DHOR < T_STEPS) {
                if (l == 0) {
                    reg_g = fmaf(w0, sh_x[2 * (t + DHOR)],
                                 fmaf(w1, sh_x[2 * (t + DHOR) + 1], bi0));
                } else {
                    reg_g = gi_in[(size_t)(t + DHOR) * G3 + j];
                }
            }

            if (j < HID) {
                const float* gi_t = sh_gi[t & (DEPTH - 1)];
                float ghr = sh_gh[j];
                float ghz = sh_gh[j + HID];
                float ghn = sh_gh[j + 2 * HID];
                float r = fast_sigmoid(gi_t[j] + ghr);
                float z = fast_sigmoid(gi_t[j + HID] + ghz);
                float n = fast_tanh(fmaf(r, ghn, gi_t[j + 2 * HID]));
                float hnew = fmaf(z, sh_h[j] - n, n);
                sh_h[j] = hnew;
                h_out[t * HID + j] = hnew;
            }
            __syncthreads();   // BAR2: new h + ring slot staged
            if (j == 0) st_release(&f_h[fh_idx(l, t)], 1);
        }
    } else if (role < 16) {
        // ================= gi CTA: layer l, 4 t-phases =====================
        const int idx = role - 4;
        const int l = idx / 4 + 1;          // 1..3
        const int phase = idx % 4;
        __shared__ __align__(16) float sh_h[HID];

        unsigned long long w[64];
        load_row128(w, W_ih_rest + ((size_t)(l - 1) * G3 + j) * HID);
        const float bi = b_ih[l * G3 + j];
        float* gi_out = g_GI + (size_t)(l - 1) * T_STEPS * G3;
        const float* h_in = g_H + (size_t)(l - 1) * T_STEPS * HID;

        for (int t = phase; t < T_STEPS; t += 4) {
            spin_until_rlx(&f_h[fh_idx(l - 1, t)]);  // relaxed: no LDS blocking
            if (j < 32) {
                reinterpret_cast<float4*>(sh_h)[j] =
                    reinterpret_cast<const float4*>(h_in + t * HID)[j];
            }
            __syncthreads();
            gi_out[(size_t)t * G3 + j] = dot128(w, sh_h) + bi;
            __syncthreads();
            if (j == 0) st_release(&f_gi[fg_idx(l, t)], 1);
        }
    } else {
        // ================= FC head CTA: 4 t-phases =========================
        const int phase = role - 16;
        __shared__ __align__(16) float sh_h[HID];
        __shared__ float sh_hid[HID];

        unsigned long long w[64];
        float b1 = 0.f;
        if (j < HID) {
            load_row128(w, fc1_w + (size_t)j * HID);
            b1 = fc1_b[j];
        }
        const float* h_in = g_H + (size_t)3 * T_STEPS * HID;

        for (int t = phase; t < T_STEPS; t += 4) {
            spin_until_rlx(&f_h[fh_idx(3, t)]);      // relaxed
            if (j < 32) {
                reinterpret_cast<float4*>(sh_h)[j] =
                    reinterpret_cast<const float4*>(h_in + t * HID)[j];
            }
            __syncthreads();
            if (j < HID) {
                sh_hid[j] = fmaxf(dot128(w, sh_h) + b1, 0.0f);
            }
            __syncthreads();
            if (j < 96) {
                int i = j >> 5;          // output row 0..2
                int lane = j & 31;
                float p = 0.f;
#pragma unroll
                for (int k = 0; k < 4; k++) {
                    int c = lane + 32 * k;
                    p = fmaf(__ldg(fc2_w + i * HID + c), sh_hid[c], p);
                }
#pragma unroll
                for (int off = 16; off > 0; off >>= 1)
                    p += __shfl_down_sync(0xffffffffu, p, off);
                if (lane == 0) out[t * 3 + i] = p + __ldg(fc2_b + i);
            }
            __syncthreads();
        }
    }
}

// ---------------------------------------------------------------------------
extern "C" void kernel_launch(void* const* d_in, const int* in_sizes, int n_in,
                              void* d_out, int out_size) {
    const float* x         = (const float*)d_in[0];
    const float* W_ih0     = (const float*)d_in[1];
    const float* W_ih_rest = (const float*)d_in[2];
    const float* W_hh      = (const float*)d_in[3];
    const float* b_ih      = (const float*)d_in[4];
    const float* b_hh      = (const float*)d_in[5];
    const float* fc1_w     = (const float*)d_in[6];
    const float* fc1_b     = (const float*)d_in[7];
    const float* fc2_w     = (const float*)d_in[8];
    const float* fc2_b     = (const float*)d_in[9];
    float* out = (float*)d_out;
    (void)in_sizes; (void)n_in; (void)out_size;

    reset_flags_kernel<<<8, 512>>>();
    pipeline_kernel<<<20, G3>>>(x, W_ih0, W_ih_rest, W_hh, b_ih, b_hh,
                                fc1_w, fc1_b, fc2_w, fc2_b, out);
}